// round 7
// baseline (speedup 1.0000x reference)
#include <cuda_runtime.h>
#include <cstdint>

// ForgetMult fused single-pass chunked scan, decoupled lookback, register-only.
// h_t = f_t*x_t + (1-f_t)*h_{t-1}
// Per chunk: a_t = prod_{s<=t}(1-f_s), b_t = local scan from 0. Then
//   h_t = b_t + a_t * h_start   (independent per t -> no second f,x read).
// No shared memory: f,x loaded once to registers; (a_t,b_t) recorded in regs.

#define FM_SEQ     2048
#define FM_NCH     16384
#define FM_NG      (FM_NCH / 4)              // 4096 float4 channel-groups
#define FM_L       8                         // timesteps per chunk
#define FM_NCHUNKS (FM_SEQ / FM_L)           // 256
#define FM_TPB     128                       // threads/block == groups per tile
#define FM_NTILES  (FM_NG / FM_TPB)          // 32
#define FM_NBLK    (FM_NCHUNKS * FM_NTILES)  // 8192

// Scratch (allocation-free rule: __device__ globals).
__device__ float4 g_pa[FM_NCHUNKS][FM_NG];
__device__ float4 g_pb[FM_NCHUNKS][FM_NG];
__device__ float4 g_inc[FM_NCHUNKS][FM_NG];
__device__ int    g_flag[FM_NCHUNKS][FM_NTILES];  // 0=none, 1=partial, 2=inclusive

__global__ void fm_init_flags()
{
    int i = blockIdx.x * blockDim.x + threadIdx.x;
    if (i < FM_NCHUNKS * FM_NTILES) ((int*)g_flag)[i] = 0;
}

__global__ __launch_bounds__(FM_TPB) void fm_fused(
    const float4* __restrict__ f, const float4* __restrict__ x,
    const float4* __restrict__ h0, float4* __restrict__ out)
{
    // chunk-major bids: lookback waits only on lower block IDs (deadlock-free
    // under in-order dispatch).
    const int chunk = blockIdx.x / FM_NTILES;
    const int tile  = blockIdx.x % FM_NTILES;
    const int tid   = threadIdx.x;
    const int g     = tile * FM_TPB + tid;

    __shared__ int s_stop;

    const size_t base = (size_t)chunk * FM_L * FM_NG + g;

    // ---- Load chunk straight to registers (16 batched LDG.128 -> deep MLP).
    float4 fv[FM_L], xv[FM_L];
#pragma unroll
    for (int t = 0; t < FM_L; t++) {
        fv[t] = __ldcs(f + base + (size_t)t * FM_NG);
        xv[t] = __ldcs(x + base + (size_t)t * FM_NG);
    }

    // ---- Pass A: incremental summary, recording (a_t, b_t) per timestep.
    float4 av[FM_L], bv[FM_L];
    {
        float4 a = make_float4(1.f, 1.f, 1.f, 1.f);
        float4 b = make_float4(0.f, 0.f, 0.f, 0.f);
#pragma unroll
        for (int t = 0; t < FM_L; t++) {
            const float4 ft = fv[t];
            const float4 xt = xv[t];
            b.x = fmaf(ft.x, xt.x - b.x, b.x);  a.x *= (1.f - ft.x);
            b.y = fmaf(ft.y, xt.y - b.y, b.y);  a.y *= (1.f - ft.y);
            b.z = fmaf(ft.z, xt.z - b.z, b.z);  a.z *= (1.f - ft.z);
            b.w = fmaf(ft.w, xt.w - b.w, b.w);  a.w *= (1.f - ft.w);
            av[t] = a;
            bv[t] = b;
        }
    }

    // ---- Resolve h_start via decoupled lookback (parallel probe).
    float4 hstart;
    if (chunk == 0) {
        hstart = __ldg(h0 + g);
    } else {
        // Publish partial summary, then flag=1.
        g_pa[chunk][g] = av[FM_L - 1];
        g_pb[chunk][g] = bv[FM_L - 1];
        __threadfence();
        __syncthreads();
        if (tid == 0) atomicExch(&g_flag[chunk][tile], 1);

        // Thread tid watches chunk-1-tid; nearest flag==2 wins via atomicMax.
        const int myj = chunk - 1 - tid;
        int stop;
        for (;;) {
            if (tid == 0) s_stop = -1;
            __syncthreads();
            if (myj >= 0) {
                int s;
                do {
                    s = *(volatile int*)&g_flag[myj][tile];
                    if (s == 0) __nanosleep(64);
                } while (s == 0);
                if (s == 2) atomicMax(&s_stop, myj);
            }
            __syncthreads();
            stop = s_stop;
            if (stop >= 0) break;
        }
        __threadfence();

        // Compose: h_start = partials(stop+1 .. chunk-1) applied to h_end(stop).
        float4 h = g_inc[stop][g];
        for (int j = stop + 1; j < chunk; j++) {
            const float4 aj = g_pa[j][g];
            const float4 bj = g_pb[j][g];
            h.x = fmaf(aj.x, h.x, bj.x);
            h.y = fmaf(aj.y, h.y, bj.y);
            h.z = fmaf(aj.z, h.z, bj.z);
            h.w = fmaf(aj.w, h.w, bj.w);
        }
        hstart = h;
    }

    // ---- Publish inclusive state ASAP (successors are spinning on it).
    if (chunk < FM_NCHUNKS - 1) {
        const float4 a = av[FM_L - 1];
        const float4 b = bv[FM_L - 1];
        float4 he;
        he.x = fmaf(a.x, hstart.x, b.x);
        he.y = fmaf(a.y, hstart.y, b.y);
        he.z = fmaf(a.z, hstart.z, b.z);
        he.w = fmaf(a.w, hstart.w, b.w);
        g_inc[chunk][g] = he;
        __threadfence();
        __syncthreads();
        if (tid == 0) atomicExch(&g_flag[chunk][tile], 2);
    }

    // ---- Output: h_t = b_t + a_t * h_start, independent per t.
#pragma unroll
    for (int t = 0; t < FM_L; t++) {
        float4 h;
        h.x = fmaf(av[t].x, hstart.x, bv[t].x);
        h.y = fmaf(av[t].y, hstart.y, bv[t].y);
        h.z = fmaf(av[t].z, hstart.z, bv[t].z);
        h.w = fmaf(av[t].w, hstart.w, bv[t].w);
        __stcs(out + base + (size_t)t * FM_NG, h);
    }
}

// ---------------- Fallback: naive per-channel scan (unexpected shapes) ----------------
__global__ void fm_naive(const float* __restrict__ f, const float* __restrict__ x,
                         const float* __restrict__ h0, float* __restrict__ out,
                         int seq, int nch)
{
    int c = blockIdx.x * blockDim.x + threadIdx.x;
    if (c >= nch) return;
    float h = h0[c];
    for (int t = 0; t < seq; t++) {
        const float ft = f[(size_t)t * nch + c];
        h = fmaf(1.f - ft, h, ft * x[(size_t)t * nch + c]);
        out[(size_t)t * nch + c] = h;
    }
}

extern "C" void kernel_launch(void* const* d_in, const int* in_sizes, int n_in,
                              void* d_out, int out_size)
{
    const float* f  = (const float*)d_in[0];
    const float* x  = (const float*)d_in[1];
    const float* h0 = (const float*)d_in[2];
    float* out      = (float*)d_out;

    const int nch = in_sizes[2];
    const int seq = in_sizes[0] / nch;

    if (seq == FM_SEQ && nch == FM_NCH) {
        fm_init_flags<<<(FM_NBLK + 255) / 256, 256>>>();
        fm_fused<<<FM_NBLK, FM_TPB>>>(
            (const float4*)f, (const float4*)x, (const float4*)h0, (float4*)out);
    } else {
        int tpb = 128;
        fm_naive<<<(nch + tpb - 1) / tpb, tpb>>>(f, x, h0, out, seq, nch);
    }
}